// round 2
// baseline (speedup 1.0000x reference)
#include <cuda_runtime.h>
#include <cstddef>

#define T_STEPS 2048
#define BATCH   64
#define HID     128
#define GATES   512   // 4*HID
#define RK      80    // weights k<RK in registers, rest in smem
#define SK      (HID - RK)   // 48

// Scratch (device globals; no allocations allowed)
__device__ float g_gx[(size_t)BATCH * T_STEPS * GATES];  // 256 MB
__device__ float g_h [(size_t)BATCH * T_STEPS * HID];    // 64 MB

// ---------------------------------------------------------------------------
// GEMM: out[r][c] = sum_k A[r][k] * W[c][k] + (bih[c]+bhh[c])
// A: [R=131072, 128], W: [512, 128], out: g_gx [R, 512]
// 128x128 tile, BK=8, 256 threads, 8x8 per thread.
// ---------------------------------------------------------------------------
__global__ __launch_bounds__(256) void gemm_kernel(
    const float* __restrict__ A, const float* __restrict__ W,
    const float* __restrict__ bih, const float* __restrict__ bhh)
{
    __shared__ float As[8][128];
    __shared__ float Bs[8][128];
    __shared__ float bias_s[128];

    const int tid  = threadIdx.x;
    const int brow = blockIdx.x * 128;
    const int bcol = blockIdx.y * 128;

    if (tid < 128) bias_s[tid] = bih[bcol + tid] + bhh[bcol + tid];

    const int lr = tid >> 1;          // 0..127
    const int kq = (tid & 1) * 4;     // 0 or 4
    const int ty = tid >> 4;          // 0..15
    const int tx = tid & 15;          // 0..15

    float acc[8][8];
#pragma unroll
    for (int i = 0; i < 8; i++)
#pragma unroll
        for (int j = 0; j < 8; j++) acc[i][j] = 0.f;

    const float* Ap = A + (size_t)(brow + lr) * HID + kq;
    const float* Wp = W + (size_t)(bcol + lr) * HID + kq;

    for (int k0 = 0; k0 < HID; k0 += 8) {
        float4 av = *(const float4*)(Ap + k0);
        float4 bv = *(const float4*)(Wp + k0);
        __syncthreads();   // previous iteration's compute done
        As[kq + 0][lr] = av.x; As[kq + 1][lr] = av.y;
        As[kq + 2][lr] = av.z; As[kq + 3][lr] = av.w;
        Bs[kq + 0][lr] = bv.x; Bs[kq + 1][lr] = bv.y;
        Bs[kq + 2][lr] = bv.z; Bs[kq + 3][lr] = bv.w;
        __syncthreads();
#pragma unroll
        for (int kk = 0; kk < 8; kk++) {
            float4 a0 = *(const float4*)&As[kk][ty * 8];
            float4 a1 = *(const float4*)&As[kk][ty * 8 + 4];
            float4 b0 = *(const float4*)&Bs[kk][tx * 8];
            float4 b1 = *(const float4*)&Bs[kk][tx * 8 + 4];
            float a[8] = {a0.x, a0.y, a0.z, a0.w, a1.x, a1.y, a1.z, a1.w};
            float bb[8] = {b0.x, b0.y, b0.z, b0.w, b1.x, b1.y, b1.z, b1.w};
#pragma unroll
            for (int i = 0; i < 8; i++)
#pragma unroll
                for (int j = 0; j < 8; j++)
                    acc[i][j] = fmaf(a[i], bb[j], acc[i][j]);
        }
    }

#pragma unroll
    for (int i = 0; i < 8; i++) {
        int row = brow + ty * 8 + i;
        float4 o0, o1;
        o0.x = acc[i][0] + bias_s[tx * 8 + 0];
        o0.y = acc[i][1] + bias_s[tx * 8 + 1];
        o0.z = acc[i][2] + bias_s[tx * 8 + 2];
        o0.w = acc[i][3] + bias_s[tx * 8 + 3];
        o1.x = acc[i][4] + bias_s[tx * 8 + 4];
        o1.y = acc[i][5] + bias_s[tx * 8 + 5];
        o1.z = acc[i][6] + bias_s[tx * 8 + 6];
        o1.w = acc[i][7] + bias_s[tx * 8 + 7];
        *(float4*)(g_gx + (size_t)row * GATES + bcol + tx * 8)     = o0;
        *(float4*)(g_gx + (size_t)row * GATES + bcol + tx * 8 + 4) = o1;
    }
}

// ---------------------------------------------------------------------------
// Recurrence: one CTA per batch row, 256 threads, thread owns gate rows
// r0 = tid and r1 = tid+256. Weights k<RK in registers, k>=RK in smem
// (k-major, conflict-free). gx prefetched one step ahead.
// ---------------------------------------------------------------------------
__device__ __forceinline__ float sigm(float x) {
    return __fdividef(1.f, 1.f + __expf(-x));
}
__device__ __forceinline__ float tanh_fast(float x) {
    float e = __expf(2.f * x);
    return 1.f - __fdividef(2.f, e + 1.f);
}

__global__ __launch_bounds__(256, 1) void rec_kernel(const float* __restrict__ whh)
{
    extern __shared__ float sm[];
    float* ws  = sm;                 // [SK * 512] k-major: ws[k][r]
    float* g_s = sm + SK * 512;      // 512 gate values
    float* h_s = g_s + GATES;        // 128 hidden

    const int tid = threadIdx.x;
    const int b   = blockIdx.x;
    const int r0  = tid;
    const int r1  = tid + 256;

    // Register weights: k in [0, RK)
    float wa[RK], wb[RK];
    {
        const float4* p0 = (const float4*)(whh + (size_t)r0 * HID);
        const float4* p1 = (const float4*)(whh + (size_t)r1 * HID);
#pragma unroll
        for (int q = 0; q < RK / 4; q++) {
            float4 v0 = p0[q];
            wa[4*q] = v0.x; wa[4*q+1] = v0.y; wa[4*q+2] = v0.z; wa[4*q+3] = v0.w;
            float4 v1 = p1[q];
            wb[4*q] = v1.x; wb[4*q+1] = v1.y; wb[4*q+2] = v1.z; wb[4*q+3] = v1.w;
        }
    }
    // Smem weights: k in [RK, 128), layout ws[(k-RK)*512 + r]
    for (int idx = tid; idx < SK * 512; idx += 256) {
        int r = idx & 511, kk = idx >> 9;
        ws[kk * 512 + r] = whh[(size_t)r * HID + RK + kk];
    }
    if (tid < HID) h_s[tid] = 0.f;
    float c = 0.f;
    __syncthreads();

    const float* gxb = g_gx + (size_t)b * T_STEPS * GATES;
    float*       hb  = g_h  + (size_t)b * T_STEPS * HID;

    float nga = gxb[r0];
    float ngb = gxb[r1];

    for (int t = 0; t < T_STEPS; t++) {
        float acc0 = nga, acc1 = ngb;
        if (t + 1 < T_STEPS) {
            nga = __ldg(gxb + (size_t)(t + 1) * GATES + r0);
            ngb = __ldg(gxb + (size_t)(t + 1) * GATES + r1);
        }
        const float4* h4 = (const float4*)h_s;
#pragma unroll
        for (int q = 0; q < RK / 4; q++) {
            float4 hv = h4[q];
            acc0 = fmaf(hv.x, wa[4*q],   acc0);
            acc0 = fmaf(hv.y, wa[4*q+1], acc0);
            acc0 = fmaf(hv.z, wa[4*q+2], acc0);
            acc0 = fmaf(hv.w, wa[4*q+3], acc0);
            acc1 = fmaf(hv.x, wb[4*q],   acc1);
            acc1 = fmaf(hv.y, wb[4*q+1], acc1);
            acc1 = fmaf(hv.z, wb[4*q+2], acc1);
            acc1 = fmaf(hv.w, wb[4*q+3], acc1);
        }
#pragma unroll
        for (int q = RK / 4; q < HID / 4; q++) {
            float4 hv = h4[q];
            const float* wsp = ws + (4 * q - RK) * 512;
            acc0 = fmaf(hv.x, wsp[r0],        acc0);
            acc0 = fmaf(hv.y, wsp[512  + r0], acc0);
            acc0 = fmaf(hv.z, wsp[1024 + r0], acc0);
            acc0 = fmaf(hv.w, wsp[1536 + r0], acc0);
            acc1 = fmaf(hv.x, wsp[r1],        acc1);
            acc1 = fmaf(hv.y, wsp[512  + r1], acc1);
            acc1 = fmaf(hv.z, wsp[1024 + r1], acc1);
            acc1 = fmaf(hv.w, wsp[1536 + r1], acc1);
        }
        g_s[r0] = acc0;
        g_s[r1] = acc1;
        __syncthreads();
        if (tid < HID) {
            float gi = g_s[tid];
            float gf = g_s[tid + 128];
            float gc = g_s[tid + 256];
            float go = g_s[tid + 384];
            float i_ = sigm(gi);
            float f_ = sigm(gf);
            float g_ = tanh_fast(gc);
            float o_ = sigm(go);
            c = f_ * c + i_ * g_;
            float hv = o_ * tanh_fast(c);
            h_s[tid] = hv;
            hb[(size_t)t * HID + tid] = hv;
        }
        __syncthreads();
    }
}

// ---------------------------------------------------------------------------
// MLP head: h_last[64,128] -> 64 -> 32 -> 10 (all linear)
// ---------------------------------------------------------------------------
__global__ __launch_bounds__(256) void mlp_kernel(
    const float* __restrict__ w1, const float* __restrict__ b1,
    const float* __restrict__ w2, const float* __restrict__ b2,
    const float* __restrict__ w3, const float* __restrict__ b3,
    float* __restrict__ out)
{
    extern __shared__ float sm[];
    float* hs = sm;          // 64*128, later reused for y2 (64*32)
    float* y1 = sm + 8192;   // 64*64

    const int tid = threadIdx.x;
    for (int idx = tid; idx < 8192; idx += 256) {
        int b = idx >> 7, j = idx & 127;
        hs[idx] = g_h[(size_t)b * T_STEPS * HID + (size_t)(T_STEPS - 1) * HID + j];
    }
    __syncthreads();
    for (int idx = tid; idx < 4096; idx += 256) {
        int b = idx >> 6, o = idx & 63;
        float s = b1[o];
#pragma unroll 8
        for (int k = 0; k < 128; k++) s = fmaf(hs[b * 128 + k], w1[o * 128 + k], s);
        y1[idx] = s;
    }
    __syncthreads();
    for (int idx = tid; idx < 2048; idx += 256) {
        int b = idx >> 5, o = idx & 31;
        float s = b2[o];
#pragma unroll 8
        for (int k = 0; k < 64; k++) s = fmaf(y1[b * 64 + k], w2[o * 64 + k], s);
        hs[idx] = s;  // reuse hs as y2 [64,32]
    }
    __syncthreads();
    for (int idx = tid; idx < 640; idx += 256) {
        int b = idx / 10, o = idx % 10;
        float s = b3[o];
#pragma unroll
        for (int k = 0; k < 32; k++) s = fmaf(hs[b * 32 + k], w3[o * 32 + k], s);
        out[idx] = s;
    }
}

// ---------------------------------------------------------------------------
extern "C" void kernel_launch(void* const* d_in, const int* in_sizes, int n_in,
                              void* d_out, int out_size)
{
    (void)in_sizes; (void)n_in; (void)out_size;
    const float* x   = (const float*)d_in[0];
    const float* wih = (const float*)d_in[1];
    const float* whh = (const float*)d_in[2];
    const float* bih = (const float*)d_in[3];
    const float* bhh = (const float*)d_in[4];
    const float* w1  = (const float*)d_in[5];
    const float* b1  = (const float*)d_in[6];
    const float* w2  = (const float*)d_in[7];
    const float* b2  = (const float*)d_in[8];
    const float* w3  = (const float*)d_in[9];
    const float* b3  = (const float*)d_in[10];

    void* hptr = nullptr;
    cudaGetSymbolAddress(&hptr, g_h);
    const float* hbuf = (const float*)hptr;

    const int REC_SMEM = (SK * 512 + GATES + HID) * 4;   // 100,864 B
    const int MLP_SMEM = (8192 + 4096) * 4;              // 49,152 B
    cudaFuncSetAttribute(rec_kernel, cudaFuncAttributeMaxDynamicSharedMemorySize, REC_SMEM);
    cudaFuncSetAttribute(mlp_kernel, cudaFuncAttributeMaxDynamicSharedMemorySize, MLP_SMEM);

    const int R = BATCH * T_STEPS;  // 131072
    for (int l = 0; l < 3; l++) {
        const float* Ain = (l == 0) ? x : hbuf;
        gemm_kernel<<<dim3(R / 128, GATES / 128), 256>>>(
            Ain, wih + (size_t)l * GATES * HID, bih + l * GATES, bhh + l * GATES);
        rec_kernel<<<BATCH, 256, REC_SMEM>>>(whh + (size_t)l * GATES * HID);
    }
    mlp_kernel<<<1, 256, MLP_SMEM>>>(w1, b1, w2, b2, w3, b3, (float*)d_out);
}

// round 3
// speedup vs baseline: 1.1863x; 1.1863x over previous
#include <cuda_runtime.h>
#include <cstddef>

#define T_STEPS 2048
#define BATCH   64
#define HID     128
#define GATES   512   // 4*HID
#define RK      96    // k-values kept in registers (as pairs)
#define RKP     (RK/2)       // 48 register pairs
#define SK      (HID - RK)   // 32 k-values in smem
#define SKP     (SK/2)       // 16 smem pairs

typedef unsigned long long ull;

// ---- packed fp32x2 helpers (sm_100+ PTX) ----------------------------------
__device__ __forceinline__ ull ffma2(ull a, ull b, ull c) {
    ull d;
    asm("fma.rn.f32x2 %0, %1, %2, %3;" : "=l"(d) : "l"(a), "l"(b), "l"(c));
    return d;
}
__device__ __forceinline__ ull pack2(float lo, float hi) {
    ull r; asm("mov.b64 %0, {%1, %2};" : "=l"(r) : "f"(lo), "f"(hi)); return r;
}
__device__ __forceinline__ float2 unpack2(ull v) {
    float2 f; asm("mov.b64 {%0, %1}, %2;" : "=f"(f.x), "=f"(f.y) : "l"(v)); return f;
}

// Scratch (device globals; no allocations allowed)
__device__ float g_gx[(size_t)BATCH * T_STEPS * GATES];  // 256 MB
__device__ float g_h [(size_t)BATCH * T_STEPS * HID];    // 64 MB

// ---------------------------------------------------------------------------
// GEMM: out[r][c] = sum_k A[r][k] * W[c][k] + (bih[c]+bhh[c])
// A: [131072, 128], W: [512, 128]. 128x128 tile, BK=8, 256 threads,
// 8x8 per thread, accumulators packed as f32x2 pairs along j.
// ---------------------------------------------------------------------------
__global__ __launch_bounds__(256) void gemm_kernel(
    const float* __restrict__ A, const float* __restrict__ W,
    const float* __restrict__ bih, const float* __restrict__ bhh)
{
    __shared__ float As[8][128];
    __shared__ float Bs[8][128];
    __shared__ float bias_s[128];

    const int tid  = threadIdx.x;
    const int brow = blockIdx.x * 128;
    const int bcol = blockIdx.y * 128;

    if (tid < 128) bias_s[tid] = bih[bcol + tid] + bhh[bcol + tid];

    const int lr = tid >> 1;          // 0..127
    const int kq = (tid & 1) * 4;     // 0 or 4
    const int ty = tid >> 4;          // 0..15
    const int tx = tid & 15;          // 0..15

    ull acc2[8][4];
#pragma unroll
    for (int i = 0; i < 8; i++)
#pragma unroll
        for (int j = 0; j < 4; j++) acc2[i][j] = 0ULL;  // (+0.f, +0.f)

    const float* Ap = A + (size_t)(brow + lr) * HID + kq;
    const float* Wp = W + (size_t)(bcol + lr) * HID + kq;

    for (int k0 = 0; k0 < HID; k0 += 8) {
        float4 av = *(const float4*)(Ap + k0);
        float4 bv = *(const float4*)(Wp + k0);
        __syncthreads();   // previous iteration's compute done
        As[kq + 0][lr] = av.x; As[kq + 1][lr] = av.y;
        As[kq + 2][lr] = av.z; As[kq + 3][lr] = av.w;
        Bs[kq + 0][lr] = bv.x; Bs[kq + 1][lr] = bv.y;
        Bs[kq + 2][lr] = bv.z; Bs[kq + 3][lr] = bv.w;
        __syncthreads();
#pragma unroll
        for (int kk = 0; kk < 8; kk++) {
            float4 a0 = *(const float4*)&As[kk][ty * 8];
            float4 a1 = *(const float4*)&As[kk][ty * 8 + 4];
            ulonglong2 bq0 = *(const ulonglong2*)&Bs[kk][tx * 8];
            ulonglong2 bq1 = *(const ulonglong2*)&Bs[kk][tx * 8 + 4];
            ull b2[4] = {bq0.x, bq0.y, bq1.x, bq1.y};
            float a[8] = {a0.x, a0.y, a0.z, a0.w, a1.x, a1.y, a1.z, a1.w};
#pragma unroll
            for (int i = 0; i < 8; i++) {
                ull ad = pack2(a[i], a[i]);
#pragma unroll
                for (int j = 0; j < 4; j++)
                    acc2[i][j] = ffma2(ad, b2[j], acc2[i][j]);
            }
        }
    }

#pragma unroll
    for (int i = 0; i < 8; i++) {
        int row = brow + ty * 8 + i;
        float2 v0 = unpack2(acc2[i][0]);
        float2 v1 = unpack2(acc2[i][1]);
        float2 v2 = unpack2(acc2[i][2]);
        float2 v3 = unpack2(acc2[i][3]);
        float4 o0, o1;
        o0.x = v0.x + bias_s[tx * 8 + 0];
        o0.y = v0.y + bias_s[tx * 8 + 1];
        o0.z = v1.x + bias_s[tx * 8 + 2];
        o0.w = v1.y + bias_s[tx * 8 + 3];
        o1.x = v2.x + bias_s[tx * 8 + 4];
        o1.y = v2.y + bias_s[tx * 8 + 5];
        o1.z = v3.x + bias_s[tx * 8 + 6];
        o1.w = v3.y + bias_s[tx * 8 + 7];
        *(float4*)(g_gx + (size_t)row * GATES + bcol + tx * 8)     = o0;
        *(float4*)(g_gx + (size_t)row * GATES + bcol + tx * 8 + 4) = o1;
    }
}

// ---------------------------------------------------------------------------
// Recurrence: one CTA per batch row, 256 threads, thread owns gate rows
// r0 = tid and r1 = tid+256. Weights as packed f32x2 k-pairs:
// pairs [0,RKP) in registers, [RKP, 64) in smem (pair-major, conflict-free).
// gx prefetched one step ahead. Matvec uses fma.rn.f32x2 throughout.
// ---------------------------------------------------------------------------
__device__ __forceinline__ float sigm(float x) {
    return __fdividef(1.f, 1.f + __expf(-x));
}
__device__ __forceinline__ float tanh_fast(float x) {
    float e = __expf(2.f * x);
    return 1.f - __fdividef(2.f, e + 1.f);
}

__global__ __launch_bounds__(256, 1) void rec_kernel(const float* __restrict__ whh)
{
    extern __shared__ char smraw[];
    ull*   ws2 = (ull*)smraw;                  // [SKP][512] packed weight pairs
    float* g_s = (float*)(ws2 + SKP * 512);    // 512 gate pre-activations
    float* h_s = g_s + GATES;                  // 128 hidden state

    const int tid = threadIdx.x;
    const int b   = blockIdx.x;
    const int r0  = tid;
    const int r1  = tid + 256;

    // Register weights: packed pairs straight from gmem (8B loads)
    ull wa2[RKP], wb2[RKP];
    {
        const ull* wp0 = (const ull*)(whh + (size_t)r0 * HID);
        const ull* wp1 = (const ull*)(whh + (size_t)r1 * HID);
#pragma unroll
        for (int q = 0; q < RKP; q++) { wa2[q] = wp0[q]; wb2[q] = wp1[q]; }
    }
    // Smem weights: pairs p in [RKP, 64), layout ws2[p*512 + r]
    for (int idx = tid; idx < SKP * 512; idx += 256) {
        int r = idx & 511, p = idx >> 9;
        ws2[idx] = ((const ull*)(whh + (size_t)r * HID))[RKP + p];
    }
    if (tid < HID) h_s[tid] = 0.f;
    float c = 0.f;
    __syncthreads();

    const float* gxb = g_gx + (size_t)b * T_STEPS * GATES;
    float*       hb  = g_h  + (size_t)b * T_STEPS * HID;

    float nga = gxb[r0];
    float ngb = gxb[r1];

    for (int t = 0; t < T_STEPS; t++) {
        ull acc0 = pack2(nga, 0.f);
        ull acc1 = pack2(ngb, 0.f);
        if (t + 1 < T_STEPS) {
            nga = __ldg(gxb + (size_t)(t + 1) * GATES + r0);
            ngb = __ldg(gxb + (size_t)(t + 1) * GATES + r1);
        }
        const ull* h2 = (const ull*)h_s;   // 64 packed h pairs (broadcast LDS)
#pragma unroll
        for (int q = 0; q < RKP; q++) {
            ull hp = h2[q];
            acc0 = ffma2(hp, wa2[q], acc0);
            acc1 = ffma2(hp, wb2[q], acc1);
        }
#pragma unroll
        for (int p = 0; p < SKP; p++) {
            ull hp = h2[RKP + p];
            acc0 = ffma2(hp, ws2[p * 512 + r0], acc0);
            acc1 = ffma2(hp, ws2[p * 512 + r1], acc1);
        }
        float2 v0 = unpack2(acc0);
        float2 v1 = unpack2(acc1);
        g_s[r0] = v0.x + v0.y;
        g_s[r1] = v1.x + v1.y;
        __syncthreads();
        if (tid < HID) {
            float gi = g_s[tid];
            float gf = g_s[tid + 128];
            float gc = g_s[tid + 256];
            float go = g_s[tid + 384];
            float i_ = sigm(gi);
            float f_ = sigm(gf);
            float g_ = tanh_fast(gc);
            float o_ = sigm(go);
            c = f_ * c + i_ * g_;
            float hv = o_ * tanh_fast(c);
            h_s[tid] = hv;
            hb[(size_t)t * HID + tid] = hv;
        }
        __syncthreads();
    }
}

// ---------------------------------------------------------------------------
// MLP head: h_last[64,128] -> 64 -> 32 -> 10 (all linear)
// ---------------------------------------------------------------------------
__global__ __launch_bounds__(256) void mlp_kernel(
    const float* __restrict__ w1, const float* __restrict__ b1,
    const float* __restrict__ w2, const float* __restrict__ b2,
    const float* __restrict__ w3, const float* __restrict__ b3,
    float* __restrict__ out)
{
    extern __shared__ float sm[];
    float* hs = sm;          // 64*128, later reused for y2 (64*32)
    float* y1 = sm + 8192;   // 64*64

    const int tid = threadIdx.x;
    for (int idx = tid; idx < 8192; idx += 256) {
        int b = idx >> 7, j = idx & 127;
        hs[idx] = g_h[(size_t)b * T_STEPS * HID + (size_t)(T_STEPS - 1) * HID + j];
    }
    __syncthreads();
    for (int idx = tid; idx < 4096; idx += 256) {
        int b = idx >> 6, o = idx & 63;
        float s = b1[o];
#pragma unroll 8
        for (int k = 0; k < 128; k++) s = fmaf(hs[b * 128 + k], w1[o * 128 + k], s);
        y1[idx] = s;
    }
    __syncthreads();
    for (int idx = tid; idx < 2048; idx += 256) {
        int b = idx >> 5, o = idx & 31;
        float s = b2[o];
#pragma unroll 8
        for (int k = 0; k < 64; k++) s = fmaf(y1[b * 64 + k], w2[o * 64 + k], s);
        hs[idx] = s;  // reuse hs as y2 [64,32]
    }
    __syncthreads();
    for (int idx = tid; idx < 640; idx += 256) {
        int b = idx / 10, o = idx % 10;
        float s = b3[o];
#pragma unroll
        for (int k = 0; k < 32; k++) s = fmaf(hs[b * 32 + k], w3[o * 32 + k], s);
        out[idx] = s;
    }
}

// ---------------------------------------------------------------------------
extern "C" void kernel_launch(void* const* d_in, const int* in_sizes, int n_in,
                              void* d_out, int out_size)
{
    (void)in_sizes; (void)n_in; (void)out_size;
    const float* x   = (const float*)d_in[0];
    const float* wih = (const float*)d_in[1];
    const float* whh = (const float*)d_in[2];
    const float* bih = (const float*)d_in[3];
    const float* bhh = (const float*)d_in[4];
    const float* w1  = (const float*)d_in[5];
    const float* b1  = (const float*)d_in[6];
    const float* w2  = (const float*)d_in[7];
    const float* b2  = (const float*)d_in[8];
    const float* w3  = (const float*)d_in[9];
    const float* b3  = (const float*)d_in[10];

    void* hptr = nullptr;
    cudaGetSymbolAddress(&hptr, g_h);
    const float* hbuf = (const float*)hptr;

    const int REC_SMEM = SKP * 512 * 8 + (GATES + HID) * 4 + 16;  // ~68 KB
    const int MLP_SMEM = (8192 + 4096) * 4;                       // 48 KB
    cudaFuncSetAttribute(rec_kernel, cudaFuncAttributeMaxDynamicSharedMemorySize, REC_SMEM);
    cudaFuncSetAttribute(mlp_kernel, cudaFuncAttributeMaxDynamicSharedMemorySize, MLP_SMEM);

    const int R = BATCH * T_STEPS;  // 131072
    for (int l = 0; l < 3; l++) {
        const float* Ain = (l == 0) ? x : hbuf;
        gemm_kernel<<<dim3(R / 128, GATES / 128), 256>>>(
            Ain, wih + (size_t)l * GATES * HID, bih + l * GATES, bhh + l * GATES);
        rec_kernel<<<BATCH, 256, REC_SMEM>>>(whh + (size_t)l * GATES * HID);
    }
    mlp_kernel<<<1, 256, MLP_SMEM>>>(w1, b1, w2, b2, w3, b3, (float*)d_out);
}

// round 4
// speedup vs baseline: 1.2278x; 1.0349x over previous
#include <cuda_runtime.h>
#include <cuda_bf16.h>
#include <cstddef>

#define T_STEPS 2048
#define BATCH   64
#define HID     128
#define GATES   512   // 4*HID
#define RK      96    // k-values kept in registers (as pairs)
#define RKP     (RK/2)       // 48 register pairs
#define SK      (HID - RK)   // 32 k-values in smem
#define SKP     (SK/2)       // 16 smem pairs

typedef unsigned long long ull;

// ---- packed fp32x2 helpers (sm_100+) --------------------------------------
__device__ __forceinline__ ull ffma2(ull a, ull b, ull c) {
    ull d;
    asm("fma.rn.f32x2 %0, %1, %2, %3;" : "=l"(d) : "l"(a), "l"(b), "l"(c));
    return d;
}
__device__ __forceinline__ ull pack2(float lo, float hi) {
    ull r; asm("mov.b64 %0, {%1, %2};" : "=l"(r) : "f"(lo), "f"(hi)); return r;
}
__device__ __forceinline__ float2 unpack2(ull v) {
    float2 f; asm("mov.b64 {%0, %1}, %2;" : "=f"(f.x), "=f"(f.y) : "l"(v)); return f;
}

// Scratch (device globals; no allocations allowed)
__device__ float g_gx[(size_t)BATCH * T_STEPS * GATES];  // 256 MB
__device__ float g_h [(size_t)BATCH * T_STEPS * HID];    // 64 MB

// ---------------------------------------------------------------------------
// Tensor-core GEMM (bf16 3-product split, fp32 accumulate):
//   gx[r][c] = sum_k A[r][k] * W[c][k] + (bih[c]+bhh[c])
// A: [131072,128] fp32, W: [512,128] fp32.
// CTA tile 128x128, 256 threads (8 warps, 4x2), warp tile 32x64.
// Whole K=128 staged in smem as bf16 hi/lo once; then 8 chunks of mma.
// ---------------------------------------------------------------------------
#define SR 136   // padded bf16 row stride (conflict-free fragment loads)

__device__ __forceinline__ void mma_bf16(float* d, const unsigned* a, const unsigned* b) {
    asm volatile(
        "mma.sync.aligned.m16n8k16.row.col.f32.bf16.bf16.f32 "
        "{%0,%1,%2,%3}, {%4,%5,%6,%7}, {%8,%9}, {%0,%1,%2,%3};"
        : "+f"(d[0]), "+f"(d[1]), "+f"(d[2]), "+f"(d[3])
        : "r"(a[0]), "r"(a[1]), "r"(a[2]), "r"(a[3]), "r"(b[0]), "r"(b[1]));
}

__global__ __launch_bounds__(256) void gemm_kernel(
    const float* __restrict__ A, const float* __restrict__ W,
    const float* __restrict__ bih, const float* __restrict__ bhh)
{
    extern __shared__ char gsm[];
    __nv_bfloat16* a_hi = (__nv_bfloat16*)gsm;                  // [128][SR]
    __nv_bfloat16* a_lo = a_hi + 128 * SR;
    __nv_bfloat16* w_hi = a_lo + 128 * SR;
    __nv_bfloat16* w_lo = w_hi + 128 * SR;
    float*         bias_s = (float*)(w_lo + 128 * SR);          // [128]

    const int tid  = threadIdx.x;
    const int brow = blockIdx.x * 128;
    const int bcol = blockIdx.y * 128;

    if (tid < 128) bias_s[tid] = bih[bcol + tid] + bhh[bcol + tid];

    // ---- load + convert A and W tiles (hi/lo bf16 split) ----
    {
        const int row = tid >> 1;            // 0..127
        const int cb  = (tid & 1) * 64;
        const float* Ar = A + (size_t)(brow + row) * HID + cb;
        const float* Wr = W + (size_t)(bcol + row) * HID + cb;
        __nv_bfloat16* ah = a_hi + row * SR + cb;
        __nv_bfloat16* al = a_lo + row * SR + cb;
        __nv_bfloat16* wh = w_hi + row * SR + cb;
        __nv_bfloat16* wl = w_lo + row * SR + cb;
#pragma unroll 4
        for (int c = 0; c < 64; c += 4) {
            float4 v = *(const float4*)(Ar + c);
            __nv_bfloat16 hx = __float2bfloat16_rn(v.x);
            __nv_bfloat16 hy = __float2bfloat16_rn(v.y);
            __nv_bfloat16 hz = __float2bfloat16_rn(v.z);
            __nv_bfloat16 hw = __float2bfloat16_rn(v.w);
            __nv_bfloat162 H0; H0.x = hx; H0.y = hy;
            __nv_bfloat162 H1; H1.x = hz; H1.y = hw;
            __nv_bfloat162 L0 = __floats2bfloat162_rn(v.x - __bfloat162float(hx),
                                                      v.y - __bfloat162float(hy));
            __nv_bfloat162 L1 = __floats2bfloat162_rn(v.z - __bfloat162float(hz),
                                                      v.w - __bfloat162float(hw));
            *(__nv_bfloat162*)(ah + c)     = H0;
            *(__nv_bfloat162*)(ah + c + 2) = H1;
            *(__nv_bfloat162*)(al + c)     = L0;
            *(__nv_bfloat162*)(al + c + 2) = L1;

            float4 u = *(const float4*)(Wr + c);
            __nv_bfloat16 gx = __float2bfloat16_rn(u.x);
            __nv_bfloat16 gy = __float2bfloat16_rn(u.y);
            __nv_bfloat16 gz = __float2bfloat16_rn(u.z);
            __nv_bfloat16 gw = __float2bfloat16_rn(u.w);
            __nv_bfloat162 G0; G0.x = gx; G0.y = gy;
            __nv_bfloat162 G1; G1.x = gz; G1.y = gw;
            __nv_bfloat162 M0 = __floats2bfloat162_rn(u.x - __bfloat162float(gx),
                                                      u.y - __bfloat162float(gy));
            __nv_bfloat162 M1 = __floats2bfloat162_rn(u.z - __bfloat162float(gz),
                                                      u.w - __bfloat162float(gw));
            *(__nv_bfloat162*)(wh + c)     = G0;
            *(__nv_bfloat162*)(wh + c + 2) = G1;
            *(__nv_bfloat162*)(wl + c)     = M0;
            *(__nv_bfloat162*)(wl + c + 2) = M1;
        }
    }
    __syncthreads();

    // ---- mma main loop ----
    const int wid    = tid >> 5;
    const int lane   = tid & 31;
    const int warp_m = wid >> 1;           // 0..3
    const int warp_n = wid & 1;            // 0..1
    const int m_base = warp_m * 32;
    const int n_base = warp_n * 64;
    const int tr = lane >> 2;              // 0..7
    const int tc = (lane & 3) * 2;         // 0,2,4,6

    float d[2][8][4];
#pragma unroll
    for (int mi = 0; mi < 2; mi++)
#pragma unroll
        for (int ni = 0; ni < 8; ni++)
#pragma unroll
            for (int e = 0; e < 4; e++) d[mi][ni][e] = 0.f;

#pragma unroll
    for (int k0 = 0; k0 < HID; k0 += 16) {
        unsigned ah[2][4], al[2][4];
#pragma unroll
        for (int mi = 0; mi < 2; mi++) {
            int r0 = m_base + mi * 16 + tr;
            ah[mi][0] = *(const unsigned*)(a_hi + (r0    ) * SR + k0 + tc);
            ah[mi][1] = *(const unsigned*)(a_hi + (r0 + 8) * SR + k0 + tc);
            ah[mi][2] = *(const unsigned*)(a_hi + (r0    ) * SR + k0 + 8 + tc);
            ah[mi][3] = *(const unsigned*)(a_hi + (r0 + 8) * SR + k0 + 8 + tc);
            al[mi][0] = *(const unsigned*)(a_lo + (r0    ) * SR + k0 + tc);
            al[mi][1] = *(const unsigned*)(a_lo + (r0 + 8) * SR + k0 + tc);
            al[mi][2] = *(const unsigned*)(a_lo + (r0    ) * SR + k0 + 8 + tc);
            al[mi][3] = *(const unsigned*)(a_lo + (r0 + 8) * SR + k0 + 8 + tc);
        }
        unsigned bh[8][2], bl[8][2];
#pragma unroll
        for (int ni = 0; ni < 8; ni++) {
            int col = n_base + ni * 8 + tr;
            bh[ni][0] = *(const unsigned*)(w_hi + col * SR + k0 + tc);
            bh[ni][1] = *(const unsigned*)(w_hi + col * SR + k0 + 8 + tc);
            bl[ni][0] = *(const unsigned*)(w_lo + col * SR + k0 + tc);
            bl[ni][1] = *(const unsigned*)(w_lo + col * SR + k0 + 8 + tc);
        }
#pragma unroll
        for (int mi = 0; mi < 2; mi++)
#pragma unroll
            for (int ni = 0; ni < 8; ni++) {
                mma_bf16(d[mi][ni], ah[mi], bh[ni]);
                mma_bf16(d[mi][ni], ah[mi], bl[ni]);
                mma_bf16(d[mi][ni], al[mi], bh[ni]);
            }
    }

    // ---- epilogue: add bias, store fp32 ----
#pragma unroll
    for (int mi = 0; mi < 2; mi++) {
        int gr0 = brow + m_base + mi * 16 + tr;
#pragma unroll
        for (int ni = 0; ni < 8; ni++) {
            int lc = n_base + ni * 8 + tc;
            float2 bv = *(const float2*)&bias_s[lc];
            float2 o0 = {d[mi][ni][0] + bv.x, d[mi][ni][1] + bv.y};
            float2 o1 = {d[mi][ni][2] + bv.x, d[mi][ni][3] + bv.y};
            *(float2*)(g_gx + (size_t)gr0 * GATES + bcol + lc)       = o0;
            *(float2*)(g_gx + (size_t)(gr0 + 8) * GATES + bcol + lc) = o1;
        }
    }
}

// ---------------------------------------------------------------------------
// Recurrence: one CTA per batch row, 256 threads. Weights as packed f32x2
// k-pairs: [0,RKP) in registers, [RKP,64) in smem. Gate phase split:
// threads 128-255 publish sigm(f), sigm(o); threads 0-127 finish with their
// own i,g registers.
// ---------------------------------------------------------------------------
__device__ __forceinline__ float sigm(float x) {
    return __fdividef(1.f, 1.f + __expf(-x));
}
__device__ __forceinline__ float tanh_fast(float x) {
    float e = __expf(2.f * x);
    return 1.f - __fdividef(2.f, e + 1.f);
}

__global__ __launch_bounds__(256, 1) void rec_kernel(const float* __restrict__ whh)
{
    extern __shared__ char smraw[];
    ull*   ws2 = (ull*)smraw;                  // [SKP][512] packed weight pairs
    float* g_s = (float*)(ws2 + SKP * 512);    // f_s[0..127], o_s[128..255]
    float* h_s = g_s + GATES;                  // 128 hidden state

    const int tid = threadIdx.x;
    const int b   = blockIdx.x;
    const int r0  = tid;
    const int r1  = tid + 256;

    ull wa2[RKP], wb2[RKP];
    {
        const ull* wp0 = (const ull*)(whh + (size_t)r0 * HID);
        const ull* wp1 = (const ull*)(whh + (size_t)r1 * HID);
#pragma unroll
        for (int q = 0; q < RKP; q++) { wa2[q] = wp0[q]; wb2[q] = wp1[q]; }
    }
    for (int idx = tid; idx < SKP * 512; idx += 256) {
        int r = idx & 511, p = idx >> 9;
        ws2[idx] = ((const ull*)(whh + (size_t)r * HID))[RKP + p];
    }
    if (tid < HID) h_s[tid] = 0.f;
    float c = 0.f;
    __syncthreads();

    const float* gxb = g_gx + (size_t)b * T_STEPS * GATES;
    float*       hb  = g_h  + (size_t)b * T_STEPS * HID;

    float nga = gxb[r0];
    float ngb = gxb[r1];

    for (int t = 0; t < T_STEPS; t++) {
        ull acc0 = pack2(nga, 0.f);
        ull acc1 = pack2(ngb, 0.f);
        if (t + 1 < T_STEPS) {
            nga = __ldg(gxb + (size_t)(t + 1) * GATES + r0);
            ngb = __ldg(gxb + (size_t)(t + 1) * GATES + r1);
        }
        const ull* h2 = (const ull*)h_s;
#pragma unroll
        for (int q = 0; q < RKP; q++) {
            ull hp = h2[q];
            acc0 = ffma2(hp, wa2[q], acc0);
            acc1 = ffma2(hp, wb2[q], acc1);
        }
#pragma unroll
        for (int p = 0; p < SKP; p++) {
            ull hp = h2[RKP + p];
            acc0 = ffma2(hp, ws2[p * 512 + r0], acc0);
            acc1 = ffma2(hp, ws2[p * 512 + r1], acc1);
        }
        float2 v0 = unpack2(acc0);
        float2 v1 = unpack2(acc1);
        float ga = v0.x + v0.y;   // gate row r0
        float gb = v1.x + v1.y;   // gate row r1
        if (tid >= 128) {
            g_s[tid - 128] = sigm(ga);   // f_j
            g_s[tid]       = sigm(gb);   // o_j
        }
        __syncthreads();
        if (tid < 128) {
            float i_ = sigm(ga);         // row tid       -> i
            float g_ = tanh_fast(gb);    // row tid+256   -> g
            c = g_s[tid] * c + i_ * g_;
            float hv = g_s[tid + 128] * tanh_fast(c);
            h_s[tid] = hv;
            hb[(size_t)t * HID + tid] = hv;
        }
        __syncthreads();
    }
}

// ---------------------------------------------------------------------------
// MLP head: h_last[64,128] -> 64 -> 32 -> 10 (all linear)
// ---------------------------------------------------------------------------
__global__ __launch_bounds__(256) void mlp_kernel(
    const float* __restrict__ w1, const float* __restrict__ b1,
    const float* __restrict__ w2, const float* __restrict__ b2,
    const float* __restrict__ w3, const float* __restrict__ b3,
    float* __restrict__ out)
{
    extern __shared__ float sm[];
    float* hs = sm;          // 64*128, later reused for y2 (64*32)
    float* y1 = sm + 8192;   // 64*64

    const int tid = threadIdx.x;
    for (int idx = tid; idx < 8192; idx += 256) {
        int b = idx >> 7, j = idx & 127;
        hs[idx] = g_h[(size_t)b * T_STEPS * HID + (size_t)(T_STEPS - 1) * HID + j];
    }
    __syncthreads();
    for (int idx = tid; idx < 4096; idx += 256) {
        int b = idx >> 6, o = idx & 63;
        float s = b1[o];
#pragma unroll 8
        for (int k = 0; k < 128; k++) s = fmaf(hs[b * 128 + k], w1[o * 128 + k], s);
        y1[idx] = s;
    }
    __syncthreads();
    for (int idx = tid; idx < 2048; idx += 256) {
        int b = idx >> 5, o = idx & 31;
        float s = b2[o];
#pragma unroll 8
        for (int k = 0; k < 64; k++) s = fmaf(y1[b * 64 + k], w2[o * 64 + k], s);
        hs[idx] = s;  // reuse hs as y2 [64,32]
    }
    __syncthreads();
    for (int idx = tid; idx < 640; idx += 256) {
        int b = idx / 10, o = idx % 10;
        float s = b3[o];
#pragma unroll
        for (int k = 0; k < 32; k++) s = fmaf(hs[b * 32 + k], w3[o * 32 + k], s);
        out[idx] = s;
    }
}

// ---------------------------------------------------------------------------
extern "C" void kernel_launch(void* const* d_in, const int* in_sizes, int n_in,
                              void* d_out, int out_size)
{
    (void)in_sizes; (void)n_in; (void)out_size;
    const float* x   = (const float*)d_in[0];
    const float* wih = (const float*)d_in[1];
    const float* whh = (const float*)d_in[2];
    const float* bih = (const float*)d_in[3];
    const float* bhh = (const float*)d_in[4];
    const float* w1  = (const float*)d_in[5];
    const float* b1  = (const float*)d_in[6];
    const float* w2  = (const float*)d_in[7];
    const float* b2  = (const float*)d_in[8];
    const float* w3  = (const float*)d_in[9];
    const float* b3  = (const float*)d_in[10];

    void* hptr = nullptr;
    cudaGetSymbolAddress(&hptr, g_h);
    const float* hbuf = (const float*)hptr;

    const int GEMM_SMEM = 4 * 128 * SR * 2 + 128 * 4;            // 139,776 B
    const int REC_SMEM  = SKP * 512 * 8 + (GATES + HID) * 4 + 16; // ~68 KB
    const int MLP_SMEM  = (8192 + 4096) * 4;                      // 48 KB
    cudaFuncSetAttribute(gemm_kernel, cudaFuncAttributeMaxDynamicSharedMemorySize, GEMM_SMEM);
    cudaFuncSetAttribute(rec_kernel,  cudaFuncAttributeMaxDynamicSharedMemorySize, REC_SMEM);
    cudaFuncSetAttribute(mlp_kernel,  cudaFuncAttributeMaxDynamicSharedMemorySize, MLP_SMEM);

    const int R = BATCH * T_STEPS;  // 131072
    for (int l = 0; l < 3; l++) {
        const float* Ain = (l == 0) ? x : hbuf;
        gemm_kernel<<<dim3(R / 128, GATES / 128), 256, GEMM_SMEM>>>(
            Ain, wih + (size_t)l * GATES * HID, bih + l * GATES, bhh + l * GATES);
        rec_kernel<<<BATCH, 256, REC_SMEM>>>(whh + (size_t)l * GATES * HID);
    }
    mlp_kernel<<<1, 256, MLP_SMEM>>>(w1, b1, w2, b2, w3, b3, (float*)d_out);
}